// round 1
// baseline (speedup 1.0000x reference)
#include <cuda_runtime.h>
#include <cstdint>

#define NN 50000
#define EE 1600000
#define DF 128
#define F1 64
#define F2 128
#define NC 40

// JAX PRNG variant: 1 = threefry_partitionable (modern JAX default), 0 = legacy
#define JAX_PARTITIONABLE 1

// ---------------- scratch (no allocation allowed) ----------------
__device__ float g_h1[NN * F1];       // x @ W1
__device__ float g_t1[NN * F1];       // layer1 output (post tanh+dropout)
__device__ float g_a2[NN * F1];       // agg(t1)
__device__ float g_h2[NN * F2];       // layer2 output (post tanh+dropout)
__device__ int   g_counts[NN];
__device__ int   g_offsets[NN + 1];
__device__ int   g_cursor[NN];
__device__ float g_dinv[NN];
__device__ int   g_csr_src[EE];
__device__ int   g_blocksums[64];
__device__ int   g_blockbase[64];
__device__ int   g_is64;

#define NB_SCAN 49   // ceil(50000/1024)

// ---------------- threefry2x32 (exact JAX algorithm) ----------------
__host__ __device__ inline void threefry2x32(uint32_t k0, uint32_t k1,
                                             uint32_t c0, uint32_t c1,
                                             uint32_t& o0, uint32_t& o1) {
  uint32_t ks2 = k0 ^ k1 ^ 0x1BD11BDAu;
  uint32_t x0 = c0 + k0, x1 = c1 + k1;
#define TFR(r) { x0 += x1; x1 = (x1 << (r)) | (x1 >> (32 - (r))); x1 ^= x0; }
  TFR(13) TFR(15) TFR(26) TFR(6)   x0 += k1;  x1 += ks2 + 1u;
  TFR(17) TFR(29) TFR(16) TFR(24)  x0 += ks2; x1 += k0 + 2u;
  TFR(13) TFR(15) TFR(26) TFR(6)   x0 += k0;  x1 += k1 + 3u;
  TFR(17) TFR(29) TFR(16) TFR(24)  x0 += k1;  x1 += ks2 + 4u;
  TFR(13) TFR(15) TFR(26) TFR(6)   x0 += ks2; x1 += k0 + 5u;
#undef TFR
  o0 = x0; o1 = x1;
}

// dropout scale for flattened index idx; n = total elements (legacy path needs it)
__device__ inline float dropout_scale(uint32_t k0, uint32_t k1, uint32_t idx, uint32_t n) {
  uint32_t o0, o1, bits;
#if JAX_PARTITIONABLE
  (void)n;
  threefry2x32(k0, k1, 0u, idx, o0, o1);
  bits = o0 ^ o1;
#else
  uint32_t half = n >> 1;
  uint32_t j = (idx < half) ? idx : (idx - half);
  threefry2x32(k0, k1, j, j + half, o0, o1);
  bits = (idx < half) ? o0 : o1;
#endif
  float u = __uint_as_float((bits >> 9) | 0x3f800000u) - 1.0f;
  return (u < 0.7f) ? (1.0f / 0.7f) : 0.0f;
}

// ---------------- edge dtype detection ----------------
__global__ void k_detect(const int* __restrict__ p) {
  __shared__ int nz;
  if (threadIdx.x == 0) nz = 0;
  __syncthreads();
  if (p[2 * threadIdx.x + 1] != 0) atomicAdd(&nz, 1);
  __syncthreads();
  if (threadIdx.x == 0) g_is64 = (nz == 0) ? 1 : 0;
}

__global__ void k_zero() {
  int i = blockIdx.x * blockDim.x + threadIdx.x;
  if (i < NN) g_counts[i] = 0;
}

__global__ void k_count(const int* __restrict__ p, int E) {
  int e = blockIdx.x * blockDim.x + threadIdx.x;
  if (e >= E) return;
  int dst = g_is64 ? p[2 * (E + e)] : p[E + e];
  atomicAdd(&g_counts[dst], 1);
}

__global__ void k_scan1() {
  __shared__ int s[1024];
  int i = blockIdx.x * 1024 + threadIdx.x;
  int c = (i < NN) ? g_counts[i] : 0;
  s[threadIdx.x] = c;
  __syncthreads();
  for (int d = 512; d > 0; d >>= 1) {
    if (threadIdx.x < d) s[threadIdx.x] += s[threadIdx.x + d];
    __syncthreads();
  }
  if (threadIdx.x == 0) g_blocksums[blockIdx.x] = s[0];
}

__global__ void k_scan2() {
  if (threadIdx.x == 0) {
    int run = 0;
    for (int j = 0; j < NB_SCAN; j++) { g_blockbase[j] = run; run += g_blocksums[j]; }
  }
}

__global__ void k_scan3() {
  __shared__ int s[1024];
  int t = threadIdx.x;
  int i = blockIdx.x * 1024 + t;
  int c = (i < NN) ? g_counts[i] : 0;
  s[t] = c;
  __syncthreads();
  for (int d = 1; d < 1024; d <<= 1) {
    int v = (t >= d) ? s[t - d] : 0;
    __syncthreads();
    s[t] += v;
    __syncthreads();
  }
  int excl = s[t] - c;
  int off = g_blockbase[blockIdx.x] + excl;
  if (i < NN) {
    g_offsets[i] = off;
    g_cursor[i] = off;
    g_dinv[i] = rsqrtf((float)(c + 1));
    if (i == NN - 1) g_offsets[NN] = off + c;
  }
}

__global__ void k_scatter(const int* __restrict__ p, int E) {
  int e = blockIdx.x * blockDim.x + threadIdx.x;
  if (e >= E) return;
  int src, dst;
  if (g_is64) { src = p[2 * e]; dst = p[2 * (E + e)]; }
  else        { src = p[e];     dst = p[E + e]; }
  int slot = atomicAdd(&g_cursor[dst], 1);
  g_csr_src[slot] = src;
}

// ---------------- aggregation: one warp per node, F=64 features ----------------
// mode 0: O = agg(H)                      (raw)
// mode 1: O = dropout(tanh(agg(H) + b))   (layer-1 epilogue, keys dk)
__global__ void k_agg(const float* __restrict__ H, float* __restrict__ O,
                      const float* __restrict__ bias, int mode,
                      uint32_t dk0, uint32_t dk1) {
  int node = blockIdx.x * (blockDim.x >> 5) + (threadIdx.x >> 5);
  if (node >= NN) return;
  int lane = threadIdx.x & 31;
  int beg = g_offsets[node], end = g_offsets[node + 1];
  float di = g_dinv[node];
  float2 acc = make_float2(0.0f, 0.0f);

  for (int base = beg; base < end; base += 32) {
    int e = base + lane;
    int s = (e < end) ? g_csr_src[e] : 0;
    float w = (e < end) ? g_dinv[s] : 0.0f;
    int cnt = min(32, end - base);
    if (cnt == 32) {
#pragma unroll 8
      for (int k = 0; k < 32; k++) {
        int ss = __shfl_sync(0xffffffffu, s, k);
        float ww = __shfl_sync(0xffffffffu, w, k);
        float2 hv = *(const float2*)&H[ss * 64 + lane * 2];
        acc.x += hv.x * ww;
        acc.y += hv.y * ww;
      }
    } else {
      for (int k = 0; k < cnt; k++) {
        int ss = __shfl_sync(0xffffffffu, s, k);
        float ww = __shfl_sync(0xffffffffu, w, k);
        float2 hv = *(const float2*)&H[ss * 64 + lane * 2];
        acc.x += hv.x * ww;
        acc.y += hv.y * ww;
      }
    }
  }

  float2 hv = *(const float2*)&H[node * 64 + lane * 2];
  float sii = di * di;
  acc.x = acc.x * di + hv.x * sii;
  acc.y = acc.y * di + hv.y * sii;

  if (mode == 1) {
    acc.x = tanhf(acc.x + bias[lane * 2]);
    acc.y = tanhf(acc.y + bias[lane * 2 + 1]);
    uint32_t j = (uint32_t)node * 64u + (uint32_t)(lane * 2);
    acc.x *= dropout_scale(dk0, dk1, j,     (uint32_t)NN * 64u);
    acc.y *= dropout_scale(dk0, dk1, j + 1, (uint32_t)NN * 64u);
  }
  *(float2*)&O[node * 64 + lane * 2] = acc;
}

// ---------------- GEMM: 64x64 tile, 256 threads, 4x4 microtile ----------------
// mode 0: C = A@B
// mode 1: C = dropout(tanh(A@B + bias))   (keys dk, logical width N)
// mode 2: C = A@B + bias
#define TM 64
#define TN 64
#define TK 32
__global__ void k_gemm(const float* __restrict__ A, const float* __restrict__ B,
                       const float* __restrict__ bias, float* __restrict__ C,
                       int M, int N, int K, int mode, uint32_t dk0, uint32_t dk1) {
  __shared__ __align__(16) float As[TK][TM + 4];
  __shared__ __align__(16) float Bs[TK][TN];
  int tid = threadIdx.x;
  int bm = blockIdx.x * TM;
  int bn = blockIdx.y * TN;
  int tm = (tid / 16) * 4;
  int tn = (tid % 16) * 4;
  float acc[4][4] = {};

  for (int k0 = 0; k0 < K; k0 += TK) {
    // A tile (transposed into smem)
#pragma unroll
    for (int i = tid; i < TM * (TK / 4); i += 256) {
      int r = i / (TK / 4), cq = i % (TK / 4);
      int row = bm + r;
      float4 v = make_float4(0, 0, 0, 0);
      if (row < M) v = *(const float4*)&A[row * K + k0 + cq * 4];
      As[cq * 4 + 0][r] = v.x;
      As[cq * 4 + 1][r] = v.y;
      As[cq * 4 + 2][r] = v.z;
      As[cq * 4 + 3][r] = v.w;
    }
    // B tile
#pragma unroll
    for (int i = tid; i < TK * (TN / 4); i += 256) {
      int kk = i / (TN / 4), nq = i % (TN / 4);
      int col = bn + nq * 4;
      float4 v = make_float4(0, 0, 0, 0);
      if (col < N) v = *(const float4*)&B[(k0 + kk) * N + col];
      *(float4*)&Bs[kk][nq * 4] = v;
    }
    __syncthreads();
#pragma unroll
    for (int kk = 0; kk < TK; kk++) {
      float4 a = *(const float4*)&As[kk][tm];
      float4 b = *(const float4*)&Bs[kk][tn];
      acc[0][0] += a.x * b.x; acc[0][1] += a.x * b.y; acc[0][2] += a.x * b.z; acc[0][3] += a.x * b.w;
      acc[1][0] += a.y * b.x; acc[1][1] += a.y * b.y; acc[1][2] += a.y * b.z; acc[1][3] += a.y * b.w;
      acc[2][0] += a.z * b.x; acc[2][1] += a.z * b.y; acc[2][2] += a.z * b.z; acc[2][3] += a.z * b.w;
      acc[3][0] += a.w * b.x; acc[3][1] += a.w * b.y; acc[3][2] += a.w * b.z; acc[3][3] += a.w * b.w;
    }
    __syncthreads();
  }

#pragma unroll
  for (int r = 0; r < 4; r++) {
#pragma unroll
    for (int c = 0; c < 4; c++) {
      int row = bm + tm + r, col = bn + tn + c;
      if (row < M && col < N) {
        float v = acc[r][c];
        if (mode == 1) {
          v = tanhf(v + bias[col]);
          v *= dropout_scale(dk0, dk1, (uint32_t)(row * N + col), (uint32_t)M * (uint32_t)N);
        } else if (mode == 2) {
          v += bias[col];
        }
        C[row * N + col] = v;
      }
    }
  }
}

// ---------------- launch ----------------
extern "C" void kernel_launch(void* const* d_in, const int* in_sizes, int n_in,
                              void* d_out, int out_size) {
  const float* x  = (const float*)d_in[0];
  const int*   ei = (const int*)d_in[1];
  const float* W1 = (const float*)d_in[2];
  const float* b1 = (const float*)d_in[3];
  const float* W2 = (const float*)d_in[4];
  const float* b2 = (const float*)d_in[5];
  const float* Wl = (const float*)d_in[6];
  const float* bl = (const float*)d_in[7];
  float* out = (float*)d_out;
  int E = in_sizes[1] / 2;

  // dropout keys: split(key(42)) on host, exactly as JAX does
  uint32_t dk1k0, dk1k1, dk2k0, dk2k1;
#if JAX_PARTITIONABLE
  threefry2x32(0u, 42u, 0u, 0u, dk1k0, dk1k1);
  threefry2x32(0u, 42u, 0u, 1u, dk2k0, dk2k1);
#else
  {
    uint32_t a0, a1, bb0, bb1;
    threefry2x32(0u, 42u, 0u, 2u, a0, bb0);   // pair (0,2)
    threefry2x32(0u, 42u, 1u, 3u, a1, bb1);   // pair (1,3)
    dk1k0 = a0; dk1k1 = a1;  dk2k0 = bb0; dk2k1 = bb1;
  }
#endif

  float *p_h1, *p_t1, *p_a2, *p_h2;
  cudaGetSymbolAddress((void**)&p_h1, g_h1);
  cudaGetSymbolAddress((void**)&p_t1, g_t1);
  cudaGetSymbolAddress((void**)&p_a2, g_a2);
  cudaGetSymbolAddress((void**)&p_h2, g_h2);

  // CSR build
  k_detect<<<1, 256>>>(ei);
  k_zero<<<(NN + 255) / 256, 256>>>();
  k_count<<<(E + 255) / 256, 256>>>(ei, E);
  k_scan1<<<NB_SCAN, 1024>>>();
  k_scan2<<<1, 32>>>();
  k_scan3<<<NB_SCAN, 1024>>>();
  k_scatter<<<(E + 255) / 256, 256>>>(ei, E);

  dim3 gemm_blk(256);
  int mb = (NN + TM - 1) / TM;   // 782

  // layer 1: h1 = x @ W1  (agg after GEMM since 64 < 128 wide)
  k_gemm<<<dim3(mb, 1), gemm_blk>>>(x, W1, nullptr, p_h1, NN, F1, DF, 0, 0u, 0u);
  // t1 = dropout(tanh(agg(h1) + b1), dk1)
  k_agg<<<(NN * 32 + 255) / 256, 256>>>(p_h1, p_t1, b1, 1, dk1k0, dk1k1);

  // layer 2: aggregate first (64 wide), then GEMM to 128
  k_agg<<<(NN * 32 + 255) / 256, 256>>>(p_t1, p_a2, nullptr, 0, 0u, 0u);
  // h2 = dropout(tanh(a2 @ W2 + b2), dk2)
  k_gemm<<<dim3(mb, 2), gemm_blk>>>(p_a2, W2, b2, p_h2, NN, F2, F1, 1, dk2k0, dk2k1);

  // head: out = h2 @ Wl + bl
  k_gemm<<<dim3(mb, 1), gemm_blk>>>(p_h2, Wl, bl, out, NN, NC, F2, 2, 0u, 0u);
}